// round 5
// baseline (speedup 1.0000x reference)
#include <cuda_runtime.h>
#include <cuda_bf16.h>

// DynamicPatchAggregator — gather, float4 along w, BRANCHLESS 2x2x2 body.
// When an axis has only one covering patch, the second slot duplicates the
// first offset with zero weight: loads hit L1 (no extra DRAM), and the body
// is straight-line => ptxas front-batches all 16 LDG.128 per thread.
// vol=192^3, patch=96^3, stride=48 -> starts {0,48,96}, 27 patches, C=2.
// Coverage complete -> upsampled global branch contributes 0; skipped.

#define VOL 192
#define PATCH 96
#define STRIDE 48
#define CH_STRIDE (PATCH*PATCH*PATCH)          // 884736
#define PATCH_STRIDE (2*CH_STRIDE)             // per-k stride (C=2)
#define OUT_CH_STRIDE (VOL*VOL*VOL)            // 7077888

__device__ __forceinline__ float gweight(int l) {
    float t = (float)(l - 48) * (1.0f / 12.0f);
    return __expf(-0.5f * t * t);
}

// Branchless per-axis info: two (offset, weight) slots; slot1 duplicates
// slot0 with weight 0 when only one patch covers x.
__device__ __forceinline__ void axis2(int x, int simul, int locmul,
                                      int* off0, int* off1,
                                      float* g0, float* g1) {
    int lo = (x - 48) / 48; lo = max(lo, 0);          // works for x in [0,192)
    int hi = min(x / 48, 2);
    int has2 = hi - lo;                               // 0 or 1
    int l0 = x - lo * STRIDE;
    int l1 = l0 - has2 * STRIDE;
    *off0 = lo * simul + l0 * locmul;
    *off1 = (lo + has2) * simul + l1 * locmul;
    *g0 = gweight(l0);
    *g1 = has2 ? gweight(l1) : 0.f;
}

__global__ __launch_bounds__(192, 6) void agg_kernel_bl(const float* __restrict__ patch,
                                                        float* __restrict__ out) {
    const int w0 = threadIdx.x * 4;              // 0,4,...,188
    const int h  = blockIdx.x * 4 + threadIdx.y; // 0..191
    const int d  = blockIdx.y;                   // 0..191

    int offD0, offD1, offH0, offH1;
    float gd0, gd1, gh0, gh1;
    axis2(d, 9 * PATCH_STRIDE, PATCH * PATCH, &offD0, &offD1, &gd0, &gd1);
    axis2(h, 3 * PATCH_STRIDE, PATCH,         &offH0, &offH1, &gh0, &gh1);

    // w axis: 4-wide group shares one covering set (boundaries 48-aligned).
    int wlo = (w0 - 48) / 48; wlo = max(wlo, 0);
    int whi = min(w0 / 48, 2);
    int whas2 = whi - wlo;
    int wl0 = w0 - wlo * STRIDE;
    int wl1 = wl0 - whas2 * STRIDE;
    const int offW0 = wlo * PATCH_STRIDE + wl0;
    const int offW1 = (wlo + whas2) * PATCH_STRIDE + wl1;

    float gw0[4], gw1[4], gsw[4];
    #pragma unroll
    for (int j = 0; j < 4; j++) {
        gw0[j] = gweight(wl0 + j);
        gw1[j] = whas2 ? gweight(wl1 + j) : 0.f;
        gsw[j] = gw0[j] + gw1[j];
    }

    // 8 unconditional base addresses (duplicates are L1 hits).
    const float* q000 = patch + offD0 + offH0 + offW0;
    const float* q001 = patch + offD0 + offH0 + offW1;
    const float* q010 = patch + offD0 + offH1 + offW0;
    const float* q011 = patch + offD0 + offH1 + offW1;
    const float* q100 = patch + offD1 + offH0 + offW0;
    const float* q101 = patch + offD1 + offH0 + offW1;
    const float* q110 = patch + offD1 + offH1 + offW0;
    const float* q111 = patch + offD1 + offH1 + offW1;

    const float w00 = gd0 * gh0, w01 = gd0 * gh1, w10 = gd1 * gh0, w11 = gd1 * gh1;

    float4 n0 = make_float4(0.f, 0.f, 0.f, 0.f);
    float4 n1 = make_float4(0.f, 0.f, 0.f, 0.f);

    #define ACC(qp, wdh, gwv)                                             \
    {                                                                     \
        const float4 v0 = __ldcs(reinterpret_cast<const float4*>(qp));    \
        const float4 v1 = __ldcs(reinterpret_cast<const float4*>((qp) + CH_STRIDE)); \
        n0.x = fmaf((wdh) * (gwv)[0], v0.x, n0.x);                        \
        n0.y = fmaf((wdh) * (gwv)[1], v0.y, n0.y);                        \
        n0.z = fmaf((wdh) * (gwv)[2], v0.z, n0.z);                        \
        n0.w = fmaf((wdh) * (gwv)[3], v0.w, n0.w);                        \
        n1.x = fmaf((wdh) * (gwv)[0], v1.x, n1.x);                        \
        n1.y = fmaf((wdh) * (gwv)[1], v1.y, n1.y);                        \
        n1.z = fmaf((wdh) * (gwv)[2], v1.z, n1.z);                        \
        n1.w = fmaf((wdh) * (gwv)[3], v1.w, n1.w);                        \
    }

    ACC(q000, w00, gw0); ACC(q001, w00, gw1);
    ACC(q010, w01, gw0); ACC(q011, w01, gw1);
    ACC(q100, w10, gw0); ACC(q101, w10, gw1);
    ACC(q110, w11, gw0); ACC(q111, w11, gw1);
    #undef ACC

    const float gdsh = (gd0 + gd1) * (gh0 + gh1);
    float4 inv;
    inv.x = __frcp_rn(fmaf(gdsh, gsw[0], 1e-20f));
    inv.y = __frcp_rn(fmaf(gdsh, gsw[1], 1e-20f));
    inv.z = __frcp_rn(fmaf(gdsh, gsw[2], 1e-20f));
    inv.w = __frcp_rn(fmaf(gdsh, gsw[3], 1e-20f));

    n0.x *= inv.x; n0.y *= inv.y; n0.z *= inv.z; n0.w *= inv.w;
    n1.x *= inv.x; n1.y *= inv.y; n1.z *= inv.z; n1.w *= inv.w;

    const int vidx = (d * VOL + h) * VOL + w0;
    __stcs(reinterpret_cast<float4*>(out + vidx), n0);
    __stcs(reinterpret_cast<float4*>(out + vidx + OUT_CH_STRIDE), n1);
}

extern "C" void kernel_launch(void* const* d_in, const int* in_sizes, int n_in,
                              void* d_out, int out_size) {
    const float* patch = (const float*)d_in[0];
    float* out = (float*)d_out;
    dim3 block(48, 4, 1);   // 48 float4-groups x 4 h-rows = 192 threads
    dim3 grid(VOL / 4, VOL, 1);
    agg_kernel_bl<<<grid, block>>>(patch, out);
}